// round 5
// baseline (speedup 1.0000x reference)
#include <cuda_runtime.h>
#include <cstdint>

#define BINS        10
#define THREADS     256
#define STAGES      6
#define CTAS_PER_SM 3
#define GRID        (148 * CTAS_PER_SM)   // 444

#define TILE_F4     THREADS               // float4s per stream per stage
#define TILE_ELEMS  (TILE_F4 * 4)         // 1024 elements per tile
#define TILE_BYTES  (TILE_F4 * 16)        // 4096 B per stream
#define STAGE_BYTES (2 * TILE_BYTES)      // 8192 B (inp + tgt)

// Dynamic smem layout
#define OFF_FULL    0
#define OFF_EMPTY   (STAGES * 8)
#define OFF_TILES   128
#define OFF_HIST    (OFF_TILES + STAGES * STAGE_BYTES)
#define SMEM_TOTAL  (OFF_HIST + BINS * THREADS * 8)   // 69760 B

// Global scratch (allocation-free). Zero at every kernel entry: zero-init at
// load, last CTA resets after writing out (graph-replay safe).
__device__ float        g_binS[BINS];
__device__ float        g_binC[BINS];
__device__ unsigned int g_ticket;

// ---------------- PTX helpers ----------------
__device__ __forceinline__ uint32_t smem_u32(const void* p) {
    uint32_t a;
    asm("{ .reg .u64 t; cvta.to.shared.u64 t, %1; cvt.u32.u64 %0, t; }"
        : "=r"(a) : "l"(p));
    return a;
}
#define MBAR_INIT(addr, cnt) \
    asm volatile("mbarrier.init.shared.b64 [%0], %1;" :: "r"(addr), "r"(cnt) : "memory")
#define MBAR_EXPECT_TX(addr, bytes) \
    asm volatile("mbarrier.arrive.expect_tx.shared.b64 _, [%0], %1;" :: "r"(addr), "r"(bytes) : "memory")
#define MBAR_ARRIVE(addr) \
    asm volatile("mbarrier.arrive.shared.b64 _, [%0];" :: "r"(addr) : "memory")
#define MBAR_WAIT(addr, par) do {                                              \
    asm volatile("{\n\t.reg .pred P;\n\t"                                      \
        "W%=:\n\t"                                                             \
        "mbarrier.try_wait.parity.acquire.cta.shared::cta.b64 P, [%0], %1, 0x989680;\n\t" \
        "@P bra.uni D%=;\n\t"                                                  \
        "bra.uni W%=;\n\t"                                                     \
        "D%=:\n\t}" :: "r"(addr), "r"(par) : "memory");                        \
} while (0)
#define MBAR_WAIT_RELAXED(addr, par) do {                                      \
    asm volatile("{\n\t.reg .pred P;\n\t"                                      \
        "W%=:\n\t"                                                             \
        "mbarrier.try_wait.parity.relaxed.cta.shared::cta.b64 P, [%0], %1, 0x989680;\n\t" \
        "@P bra.uni D%=;\n\t"                                                  \
        "bra.uni W%=;\n\t"                                                     \
        "D%=:\n\t}" :: "r"(addr), "r"(par) : "memory");                        \
} while (0)
__device__ __forceinline__ void bulk_g2s(uint32_t dst, const void* src,
                                         uint32_t bytes, uint32_t mbar) {
    asm volatile(
        "cp.async.bulk.shared::cta.global.mbarrier::complete_tx::bytes [%0], [%1], %2, [%3];"
        :: "r"(dst), "l"(src), "r"(bytes), "r"(mbar) : "memory");
}

// Per-element: g = |p-t| fp32 (bit-exact vs reference), idx = trunc(g*10)
// clipped to 9; bce = -log(t ? p : 1-p) = -log(1-g) for t in {0,1}.
// hist slot hist[idx*THREADS + tid]: 32 lanes -> 32 consecutive 8B slots,
// conflict-free regardless of idx.
__device__ __forceinline__ void ghm_accum(float p, float t, float2* hist_tid) {
    float g   = fabsf(p - t);
    int   idx = min((int)(g * 10.0f), BINS - 1);
    float bce = -__logf(1.0f - g);
    float2* slot = hist_tid + idx * THREADS;
    float2  a = *slot;
    a.x += bce;
    a.y += 1.0f;
    *slot = a;
}

__global__ void __launch_bounds__(THREADS)
ghm_tma_kernel(const float* __restrict__ inp,
               const float* __restrict__ tgt,
               int ntiles, int n,
               float* __restrict__ out) {
    extern __shared__ char smem[];
    const uint32_t sb  = smem_u32(smem);
    const int      tid = threadIdx.x;
    const int      bid = blockIdx.x;
    float2* hist = (float2*)(smem + OFF_HIST);
    __shared__ bool s_is_last;

    #pragma unroll
    for (int b = 0; b < BINS; b++)
        hist[b * THREADS + tid] = make_float2(0.0f, 0.0f);

    if (tid == 0) {
        #pragma unroll
        for (int s = 0; s < STAGES; s++) {
            MBAR_INIT(sb + OFF_FULL  + s * 8, 1);
            MBAR_INIT(sb + OFF_EMPTY + s * 8, THREADS);
        }
    }
    __syncthreads();

    // Local tiles: global tile = bid + k*GRID, k = 0..nloc-1
    int nloc = (bid < ntiles) ? (ntiles - bid + GRID - 1) / GRID : 0;

    // ---- producer prologue (thread 0): fill the pipeline ----
    int issued = 0, pstage = 0, pphase = 1;   // parity 1: first waits pass
    if (tid == 0) {
        int pre = min(STAGES, nloc);
        for (; issued < pre; issued++) {
            MBAR_WAIT_RELAXED(sb + OFF_EMPTY + pstage * 8, pphase);
            long long gt = (long long)(bid + issued * GRID);
            uint32_t dst = sb + OFF_TILES + pstage * STAGE_BYTES;
            uint32_t fb  = sb + OFF_FULL + pstage * 8;
            MBAR_EXPECT_TX(fb, STAGE_BYTES);
            bulk_g2s(dst,              (const char*)inp + gt * TILE_BYTES, TILE_BYTES, fb);
            bulk_g2s(dst + TILE_BYTES, (const char*)tgt + gt * TILE_BYTES, TILE_BYTES, fb);
            if (++pstage == STAGES) { pstage = 0; pphase ^= 1; }
        }
    }

    // ---- main loop: consume tile k, producer refills one stage ahead ----
    float2* hist_tid = &hist[tid];
    int cstage = 0, cphase = 0;
    for (int k = 0; k < nloc; k++) {
        MBAR_WAIT(sb + OFF_FULL + cstage * 8, cphase);
        const float4* P = (const float4*)(smem + OFF_TILES + cstage * STAGE_BYTES);
        const float4* T = (const float4*)((const char*)P + TILE_BYTES);
        float4 p = P[tid];
        float4 t = T[tid];
        ghm_accum(p.x, t.x, hist_tid);
        ghm_accum(p.y, t.y, hist_tid);
        ghm_accum(p.z, t.z, hist_tid);
        ghm_accum(p.w, t.w, hist_tid);
        MBAR_ARRIVE(sb + OFF_EMPTY + cstage * 8);
        if (++cstage == STAGES) { cstage = 0; cphase ^= 1; }

        if (tid == 0 && issued < nloc) {
            MBAR_WAIT_RELAXED(sb + OFF_EMPTY + pstage * 8, pphase);
            long long gt = (long long)(bid + issued * GRID);
            uint32_t dst = sb + OFF_TILES + pstage * STAGE_BYTES;
            uint32_t fb  = sb + OFF_FULL + pstage * 8;
            MBAR_EXPECT_TX(fb, STAGE_BYTES);
            bulk_g2s(dst,              (const char*)inp + gt * TILE_BYTES, TILE_BYTES, fb);
            bulk_g2s(dst + TILE_BYTES, (const char*)tgt + gt * TILE_BYTES, TILE_BYTES, fb);
            issued++;
            if (++pstage == STAGES) { pstage = 0; pphase ^= 1; }
        }
    }

    // Tail elements not covered by whole tiles (none for n = 2^25, but safe).
    for (long long i = (long long)ntiles * TILE_ELEMS + bid * THREADS + tid;
         i < n; i += (long long)GRID * THREADS)
        ghm_accum(inp[i], tgt[i], hist_tid);

    __syncthreads();

    // CTA tree reduction over the thread dimension.
    for (int s = THREADS / 2; s > 0; s >>= 1) {
        if (tid < s) {
            #pragma unroll
            for (int b = 0; b < BINS; b++) {
                float2 a = hist[b * THREADS + tid];
                float2 c = hist[b * THREADS + tid + s];
                hist[b * THREADS + tid] = make_float2(a.x + c.x, a.y + c.y);
            }
        }
        __syncthreads();
    }

    if (tid < BINS) {
        atomicAdd(&g_binS[tid], hist[tid * THREADS].x);
        atomicAdd(&g_binC[tid], hist[tid * THREADS].y);
    }
    __threadfence();
    __syncthreads();

    if (tid == 0)
        s_is_last = (atomicAdd(&g_ticket, 1u) == GRID - 1);
    __syncthreads();

    if (s_is_last && tid == 0) {
        __threadfence();
        float nb = 0.0f, accv = 0.0f;
        #pragma unroll
        for (int b = 0; b < BINS; b++) {
            float c = __ldcg(&g_binC[b]);
            float s = __ldcg(&g_binS[b]);
            if (c > 0.0f) { nb += 1.0f; accv += s / c; }
        }
        out[0] = accv / fmaxf(nb, 1.0f);
        #pragma unroll
        for (int b = 0; b < BINS; b++) { g_binS[b] = 0.0f; g_binC[b] = 0.0f; }
        g_ticket = 0u;
    }
}

extern "C" void kernel_launch(void* const* d_in, const int* in_sizes, int n_in,
                              void* d_out, int out_size) {
    const float* inp = (const float*)d_in[0];
    const float* tgt = (const float*)d_in[1];
    float* out = (float*)d_out;
    int n      = in_sizes[0];
    int ntiles = n / TILE_ELEMS;

    cudaFuncSetAttribute(ghm_tma_kernel,
                         cudaFuncAttributeMaxDynamicSharedMemorySize, SMEM_TOTAL);
    ghm_tma_kernel<<<GRID, THREADS, SMEM_TOTAL>>>(inp, tgt, ntiles, n, out);
}

// round 6
// speedup vs baseline: 1.0474x; 1.0474x over previous
#include <cuda_runtime.h>
#include <cuda_bf16.h>

#define BINS        10
#define THREADS     256
#define CTAS_PER_SM 5                 // 40 KB smem/CTA -> 5 CTAs/SM (200 KB)
#define GRID        (148 * CTAS_PER_SM)   // 740

// Global scratch (allocation-free). Invariant: zero at every kernel entry —
// zero-initialized at load, last CTA of each run resets after writing out.
__device__ float        g_binS[BINS];
__device__ float        g_binC[BINS];
__device__ unsigned int g_ticket;

// Bin index matches reference bit-for-bit: g = |p-t| in fp32,
// idx = trunc(g*10) clipped to 9 (g >= 0 so trunc == floor).
// bce = -(t*log(p) + (1-t)*log(1-p)) = -log(1 - |p-t|) for t in {0,1}.
// Per-thread-private slot hist[idx*THREADS + tid]: 32 lanes of a warp hit 32
// consecutive 8B slots -> conflict-free regardless of idx.
__device__ __forceinline__ void ghm_accum(float p, float t, float2* hist_tid) {
    float g   = fabsf(p - t);
    int   idx = min((int)(g * 10.0f), BINS - 1);
    float bce = -__logf(1.0f - g);
    float2* slot = hist_tid + idx * THREADS;
    float2  a = *slot;
    a.x += bce;
    a.y += 1.0f;
    *slot = a;
}

__global__ void __launch_bounds__(THREADS)
ghm_fused_kernel(const float* __restrict__ inp,
                 const float* __restrict__ tgt,
                 int n4, int n,
                 float* __restrict__ out) {
    // Two independent per-thread-private histogram copies: consecutive
    // accums alternate copies, so the LDS->FADD->STS RMW chains overlap
    // (one hist copy = one serialized 140-cyc chain per iteration).
    __shared__ float2 hist0[BINS * THREADS];   // 20 KB
    __shared__ float2 hist1[BINS * THREADS];   // 20 KB
    __shared__ bool   s_is_last;
    const int tid = threadIdx.x;

    #pragma unroll
    for (int b = 0; b < BINS; b++) {
        hist0[b * THREADS + tid] = make_float2(0.0f, 0.0f);
        hist1[b * THREADS + tid] = make_float2(0.0f, 0.0f);
    }
    __syncthreads();

    float2* h0 = &hist0[tid];
    float2* h1 = &hist1[tid];

    const float4* __restrict__ P4 = (const float4*)inp;
    const float4* __restrict__ T4 = (const float4*)tgt;

    // Grid-stride over float4 pairs; unroll 2 -> 4 front-batched LDG.128.
    #pragma unroll 2
    for (int i = blockIdx.x * THREADS + tid; i < n4; i += GRID * THREADS) {
        float4 p = P4[i];
        float4 t = T4[i];
        ghm_accum(p.x, t.x, h0);
        ghm_accum(p.y, t.y, h1);
        ghm_accum(p.z, t.z, h0);
        ghm_accum(p.w, t.w, h1);
    }
    // Scalar tail (n not divisible by 4).
    for (int i = n4 * 4 + blockIdx.x * THREADS + tid; i < n; i += GRID * THREADS)
        ghm_accum(inp[i], tgt[i], h0);

    __syncthreads();

    // Fold copy 1 into copy 0, then CTA tree reduction over threads.
    #pragma unroll
    for (int b = 0; b < BINS; b++) {
        float2 a = hist0[b * THREADS + tid];
        float2 c = hist1[b * THREADS + tid];
        hist0[b * THREADS + tid] = make_float2(a.x + c.x, a.y + c.y);
    }
    __syncthreads();

    for (int s = THREADS / 2; s > 0; s >>= 1) {
        if (tid < s) {
            #pragma unroll
            for (int b = 0; b < BINS; b++) {
                float2 a = hist0[b * THREADS + tid];
                float2 c = hist0[b * THREADS + tid + s];
                hist0[b * THREADS + tid] = make_float2(a.x + c.x, a.y + c.y);
            }
        }
        __syncthreads();
    }

    // Per-CTA partials into global bins.
    if (tid < BINS) {
        atomicAdd(&g_binS[tid], hist0[tid * THREADS].x);
        atomicAdd(&g_binC[tid], hist0[tid * THREADS].y);
    }
    __threadfence();
    __syncthreads();

    // Last CTA finalizes and resets state for the next graph replay.
    if (tid == 0)
        s_is_last = (atomicAdd(&g_ticket, 1u) == GRID - 1);
    __syncthreads();

    if (s_is_last && tid == 0) {
        __threadfence();
        float nb = 0.0f, accv = 0.0f;
        #pragma unroll
        for (int b = 0; b < BINS; b++) {
            float c = __ldcg(&g_binC[b]);
            float s = __ldcg(&g_binS[b]);
            if (c > 0.0f) {
                nb   += 1.0f;
                accv += s / c;
            }
        }
        out[0] = accv / fmaxf(nb, 1.0f);
        #pragma unroll
        for (int b = 0; b < BINS; b++) { g_binS[b] = 0.0f; g_binC[b] = 0.0f; }
        g_ticket = 0u;
    }
}

extern "C" void kernel_launch(void* const* d_in, const int* in_sizes, int n_in,
                              void* d_out, int out_size) {
    const float* inp = (const float*)d_in[0];
    const float* tgt = (const float*)d_in[1];
    float* out = (float*)d_out;
    int n  = in_sizes[0];
    int n4 = n >> 2;

    ghm_fused_kernel<<<GRID, THREADS>>>(inp, tgt, n4, n, out);
}

// round 7
// speedup vs baseline: 1.2463x; 1.1899x over previous
#include <cuda_runtime.h>
#include <cuda_bf16.h>

#define BINS        10
#define THREADS     256
#define CTAS_PER_SM 6
#define GRID        (148 * CTAS_PER_SM)   // 888

// Global scratch (allocation-free). Invariant: zero at every kernel entry —
// zero-initialized at load, last CTA of each run resets after writing out.
__device__ float        g_binS[BINS];
__device__ float        g_binC[BINS];
__device__ unsigned int g_ticket;

// Bin index matches reference bit-for-bit: g = |p-t| in fp32,
// idx = trunc(g*10) clipped to 9 (g >= 0 so trunc == floor).
// bce = -(t*log(p) + (1-t)*log(1-p)) = -log(1 - |p-t|) for t in {0,1}.
// Per-thread-private slot hist[idx*THREADS + tid]: 32 lanes of a warp hit 32
// consecutive 8B slots -> conflict-free regardless of idx.
__device__ __forceinline__ void ghm_accum(float p, float t, float2* hist_tid) {
    float g   = fabsf(p - t);
    int   idx = min((int)(g * 10.0f), BINS - 1);
    float bce = -__logf(1.0f - g);
    float2* slot = hist_tid + idx * THREADS;
    float2  a = *slot;
    a.x += bce;
    a.y += 1.0f;
    *slot = a;
}

__device__ __forceinline__ void ghm_accum4(float4 p, float4 t, float2* h) {
    ghm_accum(p.x, t.x, h);
    ghm_accum(p.y, t.y, h);
    ghm_accum(p.z, t.z, h);
    ghm_accum(p.w, t.w, h);
}

__global__ void __launch_bounds__(THREADS, CTAS_PER_SM)
ghm_fused_kernel(const float* __restrict__ inp,
                 const float* __restrict__ tgt,
                 int n4, int n,
                 float* __restrict__ out) {
    __shared__ float2 hist[BINS * THREADS];   // 20 KB: [bin][tid]
    __shared__ bool   s_is_last;
    const int tid = threadIdx.x;

    #pragma unroll
    for (int b = 0; b < BINS; b++)
        hist[b * THREADS + tid] = make_float2(0.0f, 0.0f);
    __syncthreads();

    float2* hist_tid = &hist[tid];

    const float4* __restrict__ P4 = (const float4*)inp;
    const float4* __restrict__ T4 = (const float4*)tgt;
    const int stride = GRID * THREADS;

    int i = blockIdx.x * THREADS + tid;

    // Main loop: 4 batched float4-pairs = 8 front-issued LDG.128 per warp,
    // THEN the histogram RMWs. Deep MLP while accums drain.
    for (; i < n4 - 3 * stride; i += 4 * stride) {
        float4 p0 = P4[i];
        float4 t0 = T4[i];
        float4 p1 = P4[i +     stride];
        float4 t1 = T4[i +     stride];
        float4 p2 = P4[i + 2 * stride];
        float4 t2 = T4[i + 2 * stride];
        float4 p3 = P4[i + 3 * stride];
        float4 t3 = T4[i + 3 * stride];
        ghm_accum4(p0, t0, hist_tid);
        ghm_accum4(p1, t1, hist_tid);
        ghm_accum4(p2, t2, hist_tid);
        ghm_accum4(p3, t3, hist_tid);
    }
    // Remainder float4 pairs.
    for (; i < n4; i += stride) {
        float4 p = P4[i];
        float4 t = T4[i];
        ghm_accum4(p, t, hist_tid);
    }
    // Scalar tail (n not divisible by 4).
    for (int j = n4 * 4 + blockIdx.x * THREADS + tid; j < n; j += stride)
        ghm_accum(inp[j], tgt[j], hist_tid);

    __syncthreads();

    // CTA tree reduction over the thread dimension, all bins per level.
    for (int s = THREADS / 2; s > 0; s >>= 1) {
        if (tid < s) {
            #pragma unroll
            for (int b = 0; b < BINS; b++) {
                float2 a = hist[b * THREADS + tid];
                float2 c = hist[b * THREADS + tid + s];
                hist[b * THREADS + tid] = make_float2(a.x + c.x, a.y + c.y);
            }
        }
        __syncthreads();
    }

    // Per-CTA partials into global bins.
    if (tid < BINS) {
        atomicAdd(&g_binS[tid], hist[tid * THREADS].x);
        atomicAdd(&g_binC[tid], hist[tid * THREADS].y);
    }
    __threadfence();
    __syncthreads();

    // Last CTA finalizes and resets state for the next graph replay.
    if (tid == 0)
        s_is_last = (atomicAdd(&g_ticket, 1u) == GRID - 1);
    __syncthreads();

    if (s_is_last && tid == 0) {
        __threadfence();
        float nb = 0.0f, accv = 0.0f;
        #pragma unroll
        for (int b = 0; b < BINS; b++) {
            float c = __ldcg(&g_binC[b]);
            float s = __ldcg(&g_binS[b]);
            if (c > 0.0f) {
                nb   += 1.0f;
                accv += s / c;
            }
        }
        out[0] = accv / fmaxf(nb, 1.0f);
        #pragma unroll
        for (int b = 0; b < BINS; b++) { g_binS[b] = 0.0f; g_binC[b] = 0.0f; }
        g_ticket = 0u;
    }
}

extern "C" void kernel_launch(void* const* d_in, const int* in_sizes, int n_in,
                              void* d_out, int out_size) {
    const float* inp = (const float*)d_in[0];
    const float* tgt = (const float*)d_in[1];
    float* out = (float*)d_out;
    int n  = in_sizes[0];
    int n4 = n >> 2;

    ghm_fused_kernel<<<GRID, THREADS>>>(inp, tgt, n4, n, out);
}